// round 10
// baseline (speedup 1.0000x reference)
#include <cuda_runtime.h>

// Problem shape (fixed by the dataset)
#define BB 64
#define LL 4096
#define EE 256
#define HH 256
#define SPLITS 9             // 64*9 = 576 CTAs = one wave at 4 CTAs/SM
#define NW 8                 // warps per CTA
#define TILE 16              // rows per TMA tile (16 KB)
#define NST 3                // ring stages
#define TILE_BYTES (TILE * EE * 4)
#define RING_BYTES (NST * TILE_BYTES)
#define SMEM_DYN (RING_BYTES + EE * 4)   // ring + wh_s

// Scratch (no allocations allowed in kernel_launch)
__device__ float g_pm[BB * SPLITS];
__device__ float g_pd[BB * SPLITS];
__device__ float g_pctx[BB * SPLITS * EE];
__device__ int   g_cnt[BB];              // zero-init; reset each run by last CTA

// ---------------- PTX helpers ----------------
__device__ __forceinline__ unsigned smem_u32(const void* p) {
    return (unsigned)__cvta_generic_to_shared(p);
}
__device__ __forceinline__ void mbar_init(unsigned mb, unsigned cnt) {
    asm volatile("mbarrier.init.shared.b64 [%0], %1;" :: "r"(mb), "r"(cnt) : "memory");
}
__device__ __forceinline__ void mbar_expect_tx(unsigned mb, unsigned bytes) {
    asm volatile("mbarrier.arrive.expect_tx.shared.b64 _, [%0], %1;"
                 :: "r"(mb), "r"(bytes) : "memory");
}
__device__ __forceinline__ void mbar_arrive(unsigned mb) {
    asm volatile("mbarrier.arrive.shared.b64 _, [%0];" :: "r"(mb) : "memory");
}
__device__ __forceinline__ void tma_bulk_1d(unsigned dst, const void* src,
                                            unsigned bytes, unsigned mb) {
    asm volatile(
        "cp.async.bulk.shared::cta.global.mbarrier::complete_tx::bytes "
        "[%0], [%1], %2, [%3];"
        :: "r"(dst), "l"(src), "r"(bytes), "r"(mb) : "memory");
}
__device__ __forceinline__ void mbar_wait(unsigned mb, unsigned parity) {
    asm volatile(
        "{\n\t"
        ".reg .pred P;\n\t"
        "LWAIT%=:\n\t"
        "mbarrier.try_wait.parity.acquire.cta.shared::cta.b64 P, [%0], %1, 0x989680;\n\t"
        "@P bra LDONE%=;\n\t"
        "bra LWAIT%=;\n\t"
        "LDONE%=:\n\t"
        "}"
        :: "r"(mb), "r"(parity) : "memory");
}

// -------------------------------------------------------------------------
// Fully fused kernel: Wh matvec + single-pass online-softmax attention over
// enc (3-stage bulk-TMA smem ring, full/empty mbarrier pipeline) + split
// combine by the last CTA of each batch. One CTA = (split s, batch b).
// Single wave: 576 CTAs at 4 CTAs/SM.
// -------------------------------------------------------------------------
__global__ __launch_bounds__(256, 4) void k_fused(const float* __restrict__ W,
                                                  const float* __restrict__ hidden,
                                                  const float* __restrict__ enc,
                                                  float* __restrict__ out) {
    extern __shared__ __align__(16) char smem_raw[];
    float4* buf  = reinterpret_cast<float4*>(smem_raw);               // ring
    float4* wh_s = reinterpret_cast<float4*>(smem_raw + RING_BYTES);  // Wh[b]

    __shared__ float sm_m[NW];
    __shared__ float sm_d[NW];
    __shared__ __align__(8) unsigned long long mbf[NST];   // full
    __shared__ __align__(8) unsigned long long mbe[NST];   // empty
    __shared__ int s_last;

    const int s = blockIdx.x;
    const int b = blockIdx.y;
    const int t = threadIdx.x;
    const int w = t >> 5;
    const int lane = t & 31;

    if (t == 0) {
#pragma unroll
        for (int i = 0; i < NST; i++) {
            mbar_init(smem_u32(&mbf[i]), 1u);
            mbar_init(smem_u32(&mbe[i]), NW);
        }
    }
    __syncthreads();

    const int begin = (s * LL) / SPLITS;
    const int end   = ((s + 1) * LL) / SPLITS;
    const int rows  = end - begin;
    const int ntiles = (rows + TILE - 1) / TILE;

    const char* gsrc = reinterpret_cast<const char*>(enc)
                     + ((size_t)b * LL + begin) * (EE * 4);

    // kick off the enc stream immediately (overlaps the Wh matvec below)
    if (t == 0) {
#pragma unroll
        for (int i = 0; i < NST; i++) {
            if (i < ntiles) {
                const int rcnt = min(TILE, rows - i * TILE);
                const unsigned bytes = (unsigned)rcnt * (EE * 4);
                mbar_expect_tx(smem_u32(&mbf[i]), bytes);
                tma_bulk_1d(smem_u32(buf) + (unsigned)i * TILE_BYTES,
                            gsrc + (size_t)i * TILE_BYTES, bytes,
                            smem_u32(&mbf[i]));
            }
        }
    }

    // ---- Wh[b,e] = sum_h W[e,h]*hidden[b,h], computed per-CTA (redundant
    //      across splits; W is L2-resident). Warp w owns e in [w*32, w*32+32),
    //      4 e's per pass with 4 interleaved shuffle chains. ----
    {
        const float4* hv = reinterpret_cast<const float4*>(hidden + (size_t)b * HH);
        const float4 h0 = __ldg(hv + lane);
        const float4 h1 = __ldg(hv + lane + 32);
        float* whf = reinterpret_cast<float*>(wh_s);
#pragma unroll
        for (int i = 0; i < 8; i++) {
            const int e0 = w * 32 + i * 4;
            float p[4];
#pragma unroll
            for (int j = 0; j < 4; j++) {
                const float4* Wr = reinterpret_cast<const float4*>(W + (size_t)(e0 + j) * HH);
                const float4 w0 = __ldg(Wr + lane);
                const float4 w1 = __ldg(Wr + lane + 32);
                p[j] = w0.x * h0.x + w0.y * h0.y + w0.z * h0.z + w0.w * h0.w
                     + w1.x * h1.x + w1.y * h1.y + w1.z * h1.z + w1.w * h1.w;
            }
#pragma unroll
            for (int sh = 16; sh >= 1; sh >>= 1) {
#pragma unroll
                for (int j = 0; j < 4; j++)
                    p[j] += __shfl_xor_sync(0xffffffffu, p[j], sh);
            }
            if (lane < 4) whf[e0 + lane] = p[lane];
        }
    }
    __syncthreads();

    const float4 wh0 = wh_s[lane];
    const float4 wh1 = wh_s[lane + 32];

    float m = -1e30f, d = 0.f;
    float4 c0 = make_float4(0.f, 0.f, 0.f, 0.f);
    float4 c1 = make_float4(0.f, 0.f, 0.f, 0.f);

    // ---- mainloop: consume tiles from the ring; warp w takes rows w, w+8 ----
    for (int tl = 0; tl < ntiles; tl++) {
        const int st = tl % NST;
        const unsigned par = (unsigned)((tl / NST) & 1);
        mbar_wait(smem_u32(&mbf[st]), par);

        const int rcnt = min(TILE, rows - tl * TILE);
        const bool hA = w < rcnt;
        const bool hB = w + 8 < rcnt;
        const float4* base = buf + st * (TILE * (EE / 4));

        float4 a0, a1, b0, b1;
        if (hA) {
            a0 = base[w * (EE / 4) + lane];
            a1 = base[w * (EE / 4) + lane + 32];
        }
        if (hB) {
            b0 = base[(w + 8) * (EE / 4) + lane];
            b1 = base[(w + 8) * (EE / 4) + lane + 32];
        }

        float pA = 0.f, pB = 0.f;
        if (hA)
            pA = a0.x * wh0.x + a0.y * wh0.y + a0.z * wh0.z + a0.w * wh0.w
               + a1.x * wh1.x + a1.y * wh1.y + a1.z * wh1.z + a1.w * wh1.w;
        if (hB)
            pB = b0.x * wh0.x + b0.y * wh0.y + b0.z * wh0.z + b0.w * wh0.w
               + b1.x * wh1.x + b1.y * wh1.y + b1.z * wh1.z + b1.w * wh1.w;

        pA += __shfl_xor_sync(0xffffffffu, pA, 16);
        pB += __shfl_xor_sync(0xffffffffu, pB, 16);
        pA += __shfl_xor_sync(0xffffffffu, pA, 8);
        pB += __shfl_xor_sync(0xffffffffu, pB, 8);
        pA += __shfl_xor_sync(0xffffffffu, pA, 4);
        pB += __shfl_xor_sync(0xffffffffu, pB, 4);
        pA += __shfl_xor_sync(0xffffffffu, pA, 2);
        pB += __shfl_xor_sync(0xffffffffu, pB, 2);
        pA += __shfl_xor_sync(0xffffffffu, pA, 1);
        pB += __shfl_xor_sync(0xffffffffu, pB, 1);

        if (hA) {
            if (pA > m) {
                const float sc = __expf(m - pA);
                d *= sc;
                c0.x *= sc; c0.y *= sc; c0.z *= sc; c0.w *= sc;
                c1.x *= sc; c1.y *= sc; c1.z *= sc; c1.w *= sc;
                m = pA;
            }
            const float e = __expf(pA - m);
            d += e;
            c0.x += e * a0.x; c0.y += e * a0.y; c0.z += e * a0.z; c0.w += e * a0.w;
            c1.x += e * a1.x; c1.y += e * a1.y; c1.z += e * a1.z; c1.w += e * a1.w;
        }
        if (hB) {
            if (pB > m) {
                const float sc = __expf(m - pB);
                d *= sc;
                c0.x *= sc; c0.y *= sc; c0.z *= sc; c0.w *= sc;
                c1.x *= sc; c1.y *= sc; c1.z *= sc; c1.w *= sc;
                m = pB;
            }
            const float e = __expf(pB - m);
            d += e;
            c0.x += e * b0.x; c0.y += e * b0.y; c0.z += e * b0.z; c0.w += e * b0.w;
            c1.x += e * b1.x; c1.y += e * b1.y; c1.z += e * b1.z; c1.w += e * b1.w;
        }

        // this warp is done with stage st (loaded values fully consumed above)
        __syncwarp();
        if (lane == 0) mbar_arrive(smem_u32(&mbe[st]));

        // producer: refill stage st with tile tl+NST once all warps released it
        const int ntl = tl + NST;
        if (t == 0 && ntl < ntiles) {
            mbar_wait(smem_u32(&mbe[st]), par);
            const int nr = min(TILE, rows - ntl * TILE);
            const unsigned bytes = (unsigned)nr * (EE * 4);
            mbar_expect_tx(smem_u32(&mbf[st]), bytes);
            tma_bulk_1d(smem_u32(buf) + (unsigned)st * TILE_BYTES,
                        gsrc + (size_t)ntl * TILE_BYTES, bytes,
                        smem_u32(&mbf[st]));
        }
    }

    // ---- CTA-level combine (ring memory reused as ctx scratch) ----
    if (lane == 0) { sm_m[w] = m; sm_d[w] = d; }
    __syncthreads();   // all warps past mainloop; ring free for reuse

    float M = sm_m[0];
#pragma unroll
    for (int i = 1; i < NW; i++) M = fmaxf(M, sm_m[i]);
    float D = 0.f;
#pragma unroll
    for (int i = 0; i < NW; i++) D += sm_d[i] * __expf(sm_m[i] - M);

    float* ctx = reinterpret_cast<float*>(smem_raw);   // NW x EE overlay
    const float sc = __expf(m - M);   // m warp-uniform after butterfly
    ctx[w * EE + lane * 4 + 0] = c0.x * sc;
    ctx[w * EE + lane * 4 + 1] = c0.y * sc;
    ctx[w * EE + lane * 4 + 2] = c0.z * sc;
    ctx[w * EE + lane * 4 + 3] = c0.w * sc;
    ctx[w * EE + 128 + lane * 4 + 0] = c1.x * sc;
    ctx[w * EE + 128 + lane * 4 + 1] = c1.y * sc;
    ctx[w * EE + 128 + lane * 4 + 2] = c1.z * sc;
    ctx[w * EE + 128 + lane * 4 + 3] = c1.w * sc;
    __syncthreads();

    float acc = 0.f;
#pragma unroll
    for (int i = 0; i < NW; i++) acc += ctx[i * EE + t];

    const int idx = b * SPLITS + s;
    g_pctx[(size_t)idx * EE + t] = acc;
    if (t == 0) { g_pm[idx] = M; g_pd[idx] = D; }

    // ---- fused split-combine: last CTA of this batch finishes the output ----
    __threadfence();
    if (t == 0) {
        const int old = atomicAdd(&g_cnt[b], 1);
        s_last = (old == SPLITS - 1);
    }
    __syncthreads();
    if (!s_last) return;
    __threadfence();   // acquire: make other CTAs' partials visible

    float pm[SPLITS];
#pragma unroll
    for (int i = 0; i < SPLITS; i++) pm[i] = g_pm[b * SPLITS + i];
    float Mg = pm[0];
#pragma unroll
    for (int i = 1; i < SPLITS; i++) Mg = fmaxf(Mg, pm[i]);
    float Dg = 0.f;
#pragma unroll
    for (int i = 0; i < SPLITS; i++) Dg += g_pd[b * SPLITS + i] * __expf(pm[i] - Mg);

    float accg = 0.f;
#pragma unroll
    for (int i = 0; i < SPLITS; i++)
        accg += g_pctx[(size_t)(b * SPLITS + i) * EE + t] * __expf(pm[i] - Mg);

    out[b * EE + t] = accg / Dg;

    if (t == 0) g_cnt[b] = 0;   // clean state for next graph replay
}

// -------------------------------------------------------------------------
// Inputs (metadata order): hidden [B,H] f32, encoderhidden [B,L,E] f32,
// W [E,H] f32, b [1] f32 (softmax-invariant -> ignored).
// Output: context [B,E] f32.
// -------------------------------------------------------------------------
extern "C" void kernel_launch(void* const* d_in, const int* in_sizes, int n_in,
                              void* d_out, int out_size) {
    const float* hidden = (const float*)d_in[0];
    const float* enc    = (const float*)d_in[1];
    const float* W      = (const float*)d_in[2];
    float* out          = (float*)d_out;

    // dynamic smem > 48 KB needs the opt-in attribute (idempotent, not an alloc)
    cudaFuncSetAttribute(k_fused, cudaFuncAttributeMaxDynamicSharedMemorySize, SMEM_DYN);

    k_fused<<<dim3(SPLITS, BB), 256, SMEM_DYN>>>(W, hidden, enc, out);
}

// round 11
// speedup vs baseline: 1.2476x; 1.2476x over previous
#include <cuda_runtime.h>

// Problem shape (fixed by the dataset)
#define BB 64
#define LL 4096
#define EE 256
#define HH 256
#define SPLITS 9             // 64*9 = 576 CTAs = one wave at 4 CTAs/SM (592 slots)
#define NW 8                 // warps per CTA

// Scratch (no allocations allowed in kernel_launch).
// Counters padded to 128B stride to avoid L2-line sharing across batches.
__device__ float g_Wh[BB * EE];
__device__ float g_pm[BB * SPLITS];
__device__ float g_pd[BB * SPLITS];
__device__ float g_pctx[BB * SPLITS * EE];
__device__ int   g_whcnt[BB * 32];       // Wh-slices-done counter (stride 32)
__device__ int   g_cnt[BB * 32];         // splits-done counter (stride 32)

// -------------------------------------------------------------------------
// Fully fused single kernel. One CTA = (split s, batch b), 8 warps,
// single wave (576 CTAs, all co-resident).
// Phase 1: the 9 CTAs of batch b cooperatively compute Wh[b,:] (each a 1/9
//          e-slice), publish to g_Wh, rendezvous on a per-batch counter.
// Phase 2: R6-proven register-LDG streaming mainloop with online softmax
//          (2 rows/warp/iter, interleaved shuffle chains, __ldcs).
// Phase 3: CTA combine -> split partials; last CTA per batch combines all
//          splits, writes out, resets counters (graph-replay clean).
// -------------------------------------------------------------------------
__global__ __launch_bounds__(256, 4) void k_fused(const float* __restrict__ W,
                                                  const float* __restrict__ hidden,
                                                  const float* __restrict__ enc,
                                                  float* __restrict__ out) {
    const int s = blockIdx.x;
    const int b = blockIdx.y;
    const int t = threadIdx.x;
    const int w = t >> 5;
    const int lane = t & 31;

    __shared__ float4 wh_s[EE / 4];
    __shared__ float sm_m[NW];
    __shared__ float sm_d[NW];
    __shared__ float sm_ctx[NW][EE];
    __shared__ int s_last;

    // ---- Phase 1: cooperative Wh slice ----
    // This CTA owns e in [ebeg, eend) (28-29 values). Warp w handles
    // e = ebeg + w + 8k, k < 4, as 4 ILP shuffle chains.
    {
        const int ebeg = (s * EE) / SPLITS;
        const int eend = ((s + 1) * EE) / SPLITS;

        const float4* hv = reinterpret_cast<const float4*>(hidden + (size_t)b * HH);
        const float4 h0 = __ldg(hv + lane);
        const float4 h1 = __ldg(hv + lane + 32);

        float p[4];
        int   ee[4];
#pragma unroll
        for (int k = 0; k < 4; k++) {
            const int e = ebeg + w + k * NW;
            ee[k] = e;
            p[k] = 0.f;
            if (e < eend) {
                const float4* Wr = reinterpret_cast<const float4*>(W + (size_t)e * HH);
                const float4 w0 = __ldg(Wr + lane);
                const float4 w1 = __ldg(Wr + lane + 32);
                p[k] = w0.x * h0.x + w0.y * h0.y + w0.z * h0.z + w0.w * h0.w
                     + w1.x * h1.x + w1.y * h1.y + w1.z * h1.z + w1.w * h1.w;
            }
        }
#pragma unroll
        for (int sh = 16; sh >= 1; sh >>= 1) {
#pragma unroll
            for (int k = 0; k < 4; k++)
                p[k] += __shfl_xor_sync(0xffffffffu, p[k], sh);
        }
        if (lane < 4 && ee[lane] < eend)
            g_Wh[b * EE + ee[lane]] = p[lane];

        __threadfence();     // publish this thread's Wh stores
        __syncthreads();     // all CTA threads published
        if (t == 0) {
            atomicAdd(&g_whcnt[b * 32], 1);
            // spin until all SPLITS slices of this batch landed
            volatile int* cnt = &g_whcnt[b * 32];
            while (*cnt < SPLITS) { __nanosleep(64); }
        }
        __syncthreads();
        __threadfence();     // acquire: other CTAs' Wh stores visible
    }

    // load full Wh[b] into smem (L2-hot), then registers
    if (t < EE / 4)
        wh_s[t] = reinterpret_cast<const float4*>(g_Wh + b * EE)[t];
    __syncthreads();

    const float4 wh0 = wh_s[lane];
    const float4 wh1 = wh_s[lane + 32];

    // ---- Phase 2: streaming mainloop (R6 structure) ----
    const float4* encb = reinterpret_cast<const float4*>(enc)
                       + (size_t)b * LL * (EE / 4);

    const int begin = (s * LL) / SPLITS;
    const int end   = ((s + 1) * LL) / SPLITS;

    float m = -1e30f, d = 0.f;
    float4 c0 = make_float4(0.f, 0.f, 0.f, 0.f);
    float4 c1 = make_float4(0.f, 0.f, 0.f, 0.f);

    int  l  = begin + w;
    bool hA = l < end;
    bool hB = l + 8 < end;
    float4 a0, a1, b0, b1;
    if (hA) {
        const float4* p0 = encb + (size_t)l * (EE / 4);
        a0 = __ldcs(p0 + lane);
        a1 = __ldcs(p0 + lane + 32);
    }
    if (hB) {
        const float4* p1 = encb + (size_t)(l + 8) * (EE / 4);
        b0 = __ldcs(p1 + lane);
        b1 = __ldcs(p1 + lane + 32);
    }

    while (hA) {
        // prefetch next pair
        const int nl = l + 16;
        const bool nA = nl < end;
        const bool nB = nl + 8 < end;
        float4 na0, na1, nb0, nb1;
        if (nA) {
            const float4* p0 = encb + (size_t)nl * (EE / 4);
            na0 = __ldcs(p0 + lane);
            na1 = __ldcs(p0 + lane + 32);
        }
        if (nB) {
            const float4* p1 = encb + (size_t)(nl + 8) * (EE / 4);
            nb0 = __ldcs(p1 + lane);
            nb1 = __ldcs(p1 + lane + 32);
        }

        // partial dots for both rows
        float pA = a0.x * wh0.x + a0.y * wh0.y + a0.z * wh0.z + a0.w * wh0.w
                 + a1.x * wh1.x + a1.y * wh1.y + a1.z * wh1.z + a1.w * wh1.w;
        float pB = 0.f;
        if (hB)
            pB = b0.x * wh0.x + b0.y * wh0.y + b0.z * wh0.z + b0.w * wh0.w
               + b1.x * wh1.x + b1.y * wh1.y + b1.z * wh1.z + b1.w * wh1.w;

        // two independent butterfly chains
        pA += __shfl_xor_sync(0xffffffffu, pA, 16);
        pB += __shfl_xor_sync(0xffffffffu, pB, 16);
        pA += __shfl_xor_sync(0xffffffffu, pA, 8);
        pB += __shfl_xor_sync(0xffffffffu, pB, 8);
        pA += __shfl_xor_sync(0xffffffffu, pA, 4);
        pB += __shfl_xor_sync(0xffffffffu, pB, 4);
        pA += __shfl_xor_sync(0xffffffffu, pA, 2);
        pB += __shfl_xor_sync(0xffffffffu, pB, 2);
        pA += __shfl_xor_sync(0xffffffffu, pA, 1);
        pB += __shfl_xor_sync(0xffffffffu, pB, 1);

        // online softmax update: row A
        if (pA > m) {
            const float sc = __expf(m - pA);
            d *= sc;
            c0.x *= sc; c0.y *= sc; c0.z *= sc; c0.w *= sc;
            c1.x *= sc; c1.y *= sc; c1.z *= sc; c1.w *= sc;
            m = pA;
        }
        {
            const float e = __expf(pA - m);
            d += e;
            c0.x += e * a0.x; c0.y += e * a0.y; c0.z += e * a0.z; c0.w += e * a0.w;
            c1.x += e * a1.x; c1.y += e * a1.y; c1.z += e * a1.z; c1.w += e * a1.w;
        }
        // row B
        if (hB) {
            if (pB > m) {
                const float sc = __expf(m - pB);
                d *= sc;
                c0.x *= sc; c0.y *= sc; c0.z *= sc; c0.w *= sc;
                c1.x *= sc; c1.y *= sc; c1.z *= sc; c1.w *= sc;
                m = pB;
            }
            const float e = __expf(pB - m);
            d += e;
            c0.x += e * b0.x; c0.y += e * b0.y; c0.z += e * b0.z; c0.w += e * b0.w;
            c1.x += e * b1.x; c1.y += e * b1.y; c1.z += e * b1.z; c1.w += e * b1.w;
        }

        a0 = na0; a1 = na1; b0 = nb0; b1 = nb1;
        hA = nA; hB = nB; l = nl;
    }

    // ---- Phase 3: CTA-level combine ----
    if (lane == 0) { sm_m[w] = m; sm_d[w] = d; }
    __syncthreads();

    float M = sm_m[0];
#pragma unroll
    for (int i = 1; i < NW; i++) M = fmaxf(M, sm_m[i]);
    float D = 0.f;
#pragma unroll
    for (int i = 0; i < NW; i++) D += sm_d[i] * __expf(sm_m[i] - M);

    const float sc = __expf(m - M);   // m is warp-uniform after butterfly
    sm_ctx[w][lane * 4 + 0] = c0.x * sc;
    sm_ctx[w][lane * 4 + 1] = c0.y * sc;
    sm_ctx[w][lane * 4 + 2] = c0.z * sc;
    sm_ctx[w][lane * 4 + 3] = c0.w * sc;
    sm_ctx[w][128 + lane * 4 + 0] = c1.x * sc;
    sm_ctx[w][128 + lane * 4 + 1] = c1.y * sc;
    sm_ctx[w][128 + lane * 4 + 2] = c1.z * sc;
    sm_ctx[w][128 + lane * 4 + 3] = c1.w * sc;
    __syncthreads();

    float acc = 0.f;
#pragma unroll
    for (int i = 0; i < NW; i++) acc += sm_ctx[i][t];

    const int idx = b * SPLITS + s;
    g_pctx[(size_t)idx * EE + t] = acc;
    if (t == 0) { g_pm[idx] = M; g_pd[idx] = D; }

    // ---- fused split-combine: last CTA of this batch finishes the output ----
    __threadfence();
    if (t == 0) {
        const int old = atomicAdd(&g_cnt[b * 32], 1);
        s_last = (old == SPLITS - 1);
    }
    __syncthreads();
    if (!s_last) return;
    __threadfence();   // acquire: other CTAs' partials visible

    float pm[SPLITS];
#pragma unroll
    for (int i = 0; i < SPLITS; i++) pm[i] = g_pm[b * SPLITS + i];
    float Mg = pm[0];
#pragma unroll
    for (int i = 1; i < SPLITS; i++) Mg = fmaxf(Mg, pm[i]);
    float Dg = 0.f;
#pragma unroll
    for (int i = 0; i < SPLITS; i++) Dg += g_pd[b * SPLITS + i] * __expf(pm[i] - Mg);

    float accg = 0.f;
#pragma unroll
    for (int i = 0; i < SPLITS; i++)
        accg += g_pctx[(size_t)(b * SPLITS + i) * EE + t] * __expf(pm[i] - Mg);

    out[b * EE + t] = accg / Dg;

    // clean state for next graph replay
    if (t == 0) {
        g_cnt[b * 32] = 0;
        g_whcnt[b * 32] = 0;
    }
}

// -------------------------------------------------------------------------
// Inputs (metadata order): hidden [B,H] f32, encoderhidden [B,L,E] f32,
// W [E,H] f32, b [1] f32 (softmax-invariant -> ignored).
// Output: context [B,E] f32.
// -------------------------------------------------------------------------
extern "C" void kernel_launch(void* const* d_in, const int* in_sizes, int n_in,
                              void* d_out, int out_size) {
    const float* hidden = (const float*)d_in[0];
    const float* enc    = (const float*)d_in[1];
    const float* W      = (const float*)d_in[2];
    float* out          = (float*)d_out;

    k_fused<<<dim3(SPLITS, BB), 256>>>(W, hidden, enc, out);
}